// round 1
// baseline (speedup 1.0000x reference)
#include <cuda_runtime.h>
#include <cuda_bf16.h>
#include <cstdint>

// ---------------- problem constants ----------------
#define BATCH   8
#define C2DIM   128
#define C3DIM   256
#define HDIM    28
#define WDIM    28
#define H3      14
#define W3      14
#define CDIM    384                 // C2 + C3
#define NPATCH  6272                // B*H*W
#define MBANK   30000

// ---------------- GEMM tiling ----------------
#define BN      64                  // patches per block
#define BM      128                 // bank rows per tile
#define BK      32                  // k chunk
#define MSPLIT  4
#define MS_ROWS 7500                // MBANK / MSPLIT (exact)
#define MS_TILES ((MS_ROWS + BM - 1) / BM)   // 59

#define AS_STRIDE 388               // 384 + 4 pad (keeps 16B align, breaks bank alias)
#define BS_STRIDE 132               // 128 + 4 pad (16B-aligned row stride)

#define SMEM_FLOATS (BN * AS_STRIDE + BK * BS_STRIDE + BM)
#define SMEM_BYTES  (SMEM_FLOATS * 4)

// ---------------- scratch (no allocs allowed) ----------------
__device__ __align__(16) float g_patches[(size_t)NPATCH * CDIM]; // 9.6 MB
__device__ float g_xsq[NPATCH];
__device__ float g_msq[MBANK];
__device__ float g_part[MSPLIT * NPATCH];

// =====================================================================
// 1) Embed: bilinear upsample f3 (14->28, half-pixel, edge clamp) and
//    concat with f2 into patches[n][c], n = b*784 + h*28 + w.
// =====================================================================
__global__ void embed_kernel(const float* __restrict__ f2,
                             const float* __restrict__ f3) {
    int idx = blockIdx.x * blockDim.x + threadIdx.x;
    if (idx >= NPATCH * CDIM) return;
    int n = idx / CDIM;
    int c = idx - n * CDIM;
    int b = n / (HDIM * WDIM);
    int hw = n - b * (HDIM * WDIM);
    int h = hw / WDIM;
    int w = hw - h * WDIM;

    float val;
    if (c < C2DIM) {
        val = f2[(((size_t)b * C2DIM + c) * HDIM + h) * WDIM + w];
    } else {
        int c3 = c - C2DIM;
        // src = (dst + 0.5) * 0.5 - 0.5
        float sh = h * 0.5f - 0.25f;
        float sw = w * 0.5f - 0.25f;
        int h0 = (int)floorf(sh);
        int w0 = (int)floorf(sw);
        float th = sh - (float)h0;
        float tw = sw - (float)w0;
        int h0c = h0 < 0 ? 0 : h0;        int h1c = h0 + 1 > H3 - 1 ? H3 - 1 : h0 + 1;
        int w0c = w0 < 0 ? 0 : w0;        int w1c = w0 + 1 > W3 - 1 ? W3 - 1 : w0 + 1;
        const float* base = f3 + ((size_t)b * C3DIM + c3) * (H3 * W3);
        float v00 = base[h0c * W3 + w0c];
        float v01 = base[h0c * W3 + w1c];
        float v10 = base[h1c * W3 + w0c];
        float v11 = base[h1c * W3 + w1c];
        val = (1.f - th) * ((1.f - tw) * v00 + tw * v01)
            +        th  * ((1.f - tw) * v10 + tw * v11);
    }
    g_patches[(size_t)n * CDIM + c] = val;
}

// =====================================================================
// 2) Row squared-norms (one warp per row, 384 cols)
// =====================================================================
__device__ __forceinline__ void rowsq_impl(const float* __restrict__ src,
                                           float* __restrict__ dst, int rows) {
    int warp = (blockIdx.x * blockDim.x + threadIdx.x) >> 5;
    int lane = threadIdx.x & 31;
    if (warp >= rows) return;
    const float* r = src + (size_t)warp * CDIM;
    float s = 0.f;
    #pragma unroll
    for (int j = 0; j < CDIM / 32; ++j) {
        float v = r[lane + j * 32];
        s += v * v;
    }
    #pragma unroll
    for (int off = 16; off; off >>= 1)
        s += __shfl_xor_sync(0xffffffffu, s, off);
    if (lane == 0) dst[warp] = s;
}

__global__ void xsq_kernel() { rowsq_impl(g_patches, g_xsq, NPATCH); }
__global__ void msq_kernel(const float* __restrict__ bank) { rowsq_impl(bank, g_msq, MBANK); }

// =====================================================================
// 3) Distance GEMM + fused 1-NN min.
//    Block: 256 threads, tile BN=64 patches x (MS_ROWS bank rows of its split).
//    A tile (64x384 fp32) fully resident in SMEM; B staged in 128x32 chunks.
//    Per-thread 4x8 micro-tile using packed fma.rn.f32x2 (FFMA2).
//    Tracks min over (||m||^2 - 2 x.m); ||x||^2 added in finalize.
// =====================================================================
__global__ void dist_min_kernel(const float* __restrict__ bank) {
    extern __shared__ float smem[];
    float* As    = smem;                         // BN * AS_STRIDE
    float* Bs    = As + BN * AS_STRIDE;          // BK * BS_STRIDE
    float* msq_s = Bs + BK * BS_STRIDE;          // BM

    const int tid   = threadIdx.x;
    const int n0    = blockIdx.x * BN;
    const int split = blockIdx.y;

    // ---- load A tile (64 x 384) with float4 ----
    #pragma unroll 1
    for (int i = tid; i < BN * (CDIM / 4); i += 256) {
        int r  = i / (CDIM / 4);
        int kq = i - r * (CDIM / 4);
        float4 v = *(const float4*)(g_patches + (size_t)(n0 + r) * CDIM + kq * 4);
        *(float4*)(As + r * AS_STRIDE + kq * 4) = v;
    }

    const int gi = tid >> 4;        // 0..15 : row group
    const int gj = tid & 15;        // 0..15 : col group
    const int rowbase = gi * 4;
    const int m0 = gj * 8;

    const int mbase  = split * MS_ROWS;
    const int mlimit = mbase + MS_ROWS;          // == exact bound, MS_ROWS*MSPLIT == MBANK

    float minv[4] = {3.0e38f, 3.0e38f, 3.0e38f, 3.0e38f};

    const float* Arow = As + rowbase * AS_STRIDE;

    #pragma unroll 1
    for (int mt = 0; mt < MS_TILES; ++mt) {
        const int mrow0 = mbase + mt * BM;

        unsigned long long acc[4][4];
        #pragma unroll
        for (int i = 0; i < 4; ++i)
            #pragma unroll
            for (int j = 0; j < 4; ++j)
                acc[i][j] = 0ULL;

        #pragma unroll 1
        for (int kc = 0; kc < CDIM / BK; ++kc) {
            __syncthreads();   // protect Bs (and msq_s/min-read of previous tile)
            if (kc == 0 && tid < BM) {
                int mr = mrow0 + tid;
                msq_s[tid] = (mr < mlimit) ? g_msq[mr] : 3.0e38f;
            }
            // load B chunk (BM rows x BK cols), stored transposed Bs[k][m]
            #pragma unroll
            for (int i = tid; i < (BK * BM) / 4; i += 256) {
                int r  = i >> 3;        // 0..127
                int kq = i & 7;         // 0..7
                float4 v = make_float4(0.f, 0.f, 0.f, 0.f);
                int grow = mrow0 + r;
                if (grow < mlimit)
                    v = *(const float4*)(bank + (size_t)grow * CDIM + kc * BK + kq * 4);
                int kb = kq * 4;
                Bs[(kb + 0) * BS_STRIDE + r] = v.x;
                Bs[(kb + 1) * BS_STRIDE + r] = v.y;
                Bs[(kb + 2) * BS_STRIDE + r] = v.z;
                Bs[(kb + 3) * BS_STRIDE + r] = v.w;
            }
            __syncthreads();

            const float* Ak = Arow + kc * BK;
            #pragma unroll
            for (int kk = 0; kk < BK; ++kk) {
                const float* bp = Bs + kk * BS_STRIDE + m0;
                unsigned long long b0 = *(const unsigned long long*)(bp + 0);
                unsigned long long b1 = *(const unsigned long long*)(bp + 2);
                unsigned long long b2 = *(const unsigned long long*)(bp + 4);
                unsigned long long b3 = *(const unsigned long long*)(bp + 6);
                #pragma unroll
                for (int i = 0; i < 4; ++i) {
                    unsigned int au = __float_as_uint(Ak[i * AS_STRIDE + kk]);
                    unsigned long long ad;
                    asm("mov.b64 %0, {%1, %1};" : "=l"(ad) : "r"(au));
                    asm("fma.rn.f32x2 %0, %1, %2, %0;" : "+l"(acc[i][0]) : "l"(ad), "l"(b0));
                    asm("fma.rn.f32x2 %0, %1, %2, %0;" : "+l"(acc[i][1]) : "l"(ad), "l"(b1));
                    asm("fma.rn.f32x2 %0, %1, %2, %0;" : "+l"(acc[i][2]) : "l"(ad), "l"(b2));
                    asm("fma.rn.f32x2 %0, %1, %2, %0;" : "+l"(acc[i][3]) : "l"(ad), "l"(b3));
                }
            }
        }

        // fold tile into running min of (msq - 2*dot)
        #pragma unroll
        for (int i = 0; i < 4; ++i) {
            #pragma unroll
            for (int j = 0; j < 4; ++j) {
                float lo = __uint_as_float((unsigned int)(acc[i][j]));
                float hi = __uint_as_float((unsigned int)(acc[i][j] >> 32));
                float v0 = msq_s[m0 + 2 * j + 0] - 2.f * lo;
                float v1 = msq_s[m0 + 2 * j + 1] - 2.f * hi;
                minv[i] = fminf(minv[i], fminf(v0, v1));
            }
        }
    }

    // reduce across the 16 threads of the column-group (lanes stay in 16-halves)
    #pragma unroll
    for (int i = 0; i < 4; ++i) {
        float v = minv[i];
        #pragma unroll
        for (int off = 8; off; off >>= 1)
            v = fminf(v, __shfl_xor_sync(0xffffffffu, v, off));
        if (gj == 0)
            g_part[split * NPATCH + n0 + rowbase + i] = v;
    }
}

// =====================================================================
// 4) Finalize: reduce splits, add ||x||^2, clamp, sqrt -> patch scores
// =====================================================================
__global__ void finalize_kernel(float* __restrict__ out) {
    int n = blockIdx.x * blockDim.x + threadIdx.x;
    if (n >= NPATCH) return;
    float m = fminf(fminf(g_part[n], g_part[NPATCH + n]),
                    fminf(g_part[2 * NPATCH + n], g_part[3 * NPATCH + n]));
    float d2 = g_xsq[n] + m;
    d2 = fmaxf(d2, 1e-12f);
    out[n] = sqrtf(d2);
}

// =====================================================================
// 5) Per-image max
// =====================================================================
__global__ void img_max_kernel(float* __restrict__ out) {
    __shared__ float red[8];
    int b = blockIdx.x;
    int tid = threadIdx.x;
    float v = -3.0e38f;
    for (int i = tid; i < HDIM * WDIM; i += blockDim.x)
        v = fmaxf(v, out[b * (HDIM * WDIM) + i]);
    #pragma unroll
    for (int off = 16; off; off >>= 1)
        v = fmaxf(v, __shfl_xor_sync(0xffffffffu, v, off));
    if ((tid & 31) == 0) red[tid >> 5] = v;
    __syncthreads();
    if (tid < 8) {
        v = red[tid];
        #pragma unroll
        for (int off = 4; off; off >>= 1)
            v = fmaxf(v, __shfl_xor_sync(0x000000ffu, v, off));
        if (tid == 0) out[NPATCH + b] = v;
    }
}

// =====================================================================
extern "C" void kernel_launch(void* const* d_in, const int* in_sizes, int n_in,
                              void* d_out, int out_size) {
    const float* f2   = (const float*)d_in[0];
    const float* f3   = (const float*)d_in[1];
    const float* bank = (const float*)d_in[2];
    float* out = (float*)d_out;

    cudaFuncSetAttribute(dist_min_kernel,
                         cudaFuncAttributeMaxDynamicSharedMemorySize, SMEM_BYTES);

    embed_kernel<<<(NPATCH * CDIM + 255) / 256, 256>>>(f2, f3);
    xsq_kernel<<<(NPATCH * 32 + 255) / 256, 256>>>();
    msq_kernel<<<(MBANK * 32 + 255) / 256, 256>>>(bank);

    dim3 grid(NPATCH / BN, MSPLIT);
    dist_min_kernel<<<grid, 256, SMEM_BYTES>>>(bank);

    finalize_kernel<<<(NPATCH + 255) / 256, 256>>>(out);
    if (out_size >= NPATCH + BATCH)
        img_max_kernel<<<BATCH, 256>>>(out);
}

// round 3
// speedup vs baseline: 16.8749x; 16.8749x over previous
#include <cuda_runtime.h>
#include <cuda_bf16.h>
#include <cstdint>

// ---------------- problem constants ----------------
#define BATCH   8
#define C2DIM   128
#define C3DIM   256
#define HDIM    28
#define WDIM    28
#define H3      14
#define W3      14
#define CDIM    384
#define NPATCH  6272
#define MBANK   30000
#define MBANK_PAD 30720             // 3 splits * 40 tiles * 256 rows

// ---------------- tiling ----------------
#define MSPLIT   3
#define TILE_M   128                // patches per CTA
#define TILE_N   256                // bank rows per CTA tile
#define NTILES   49                 // NPATCH / TILE_M
#define BTILES   40                 // bank tiles per split (40*256 = 10240)
#define CHUNKS   (BTILES * 6)       // k-chunks of 64 per split stream

#define ASTRIDE  392                // bf16 elems per A row (384 + 8 pad)
#define ABYTES   (128 * ASTRIDE * 2)    // 100352
#define BROWB    144                // bytes per B row (64 bf16 + 8 pad)
#define BBUF     (TILE_N * BROWB)   // 36864
#define SM_TOTAL (ABYTES + 2 * BBUF)    // 174080

// ---------------- scratch ----------------
__device__ __align__(16) __nv_bfloat16 g_pat_bf[(size_t)NPATCH * CDIM];
__device__ __align__(16) __nv_bfloat16 g_bank_bf[(size_t)MBANK_PAD * CDIM];
__device__ float g_xsq[NPATCH];
__device__ float g_msq[MBANK_PAD];
__device__ float g_part[MSPLIT * NPATCH];

__device__ __forceinline__ uint32_t s2u(const void* p) {
    uint32_t r;
    asm("{ .reg .u64 t; cvta.to.shared.u64 t, %1; cvt.u32.u64 %0, t; }"
        : "=r"(r) : "l"(p));
    return r;
}

// ============================ prep kernels ============================
__global__ void embed_kernel(const float* __restrict__ f2,
                             const float* __restrict__ f3) {
    int idx = blockIdx.x * blockDim.x + threadIdx.x;
    if (idx >= NPATCH * CDIM) return;
    int n = idx / CDIM;
    int c = idx - n * CDIM;
    int b = n / (HDIM * WDIM);
    int hw = n - b * (HDIM * WDIM);
    int h = hw / WDIM;
    int w = hw - h * WDIM;

    float val;
    if (c < C2DIM) {
        val = f2[(((size_t)b * C2DIM + c) * HDIM + h) * WDIM + w];
    } else {
        int c3 = c - C2DIM;
        float sh = h * 0.5f - 0.25f;
        float sw = w * 0.5f - 0.25f;
        int h0 = (int)floorf(sh);
        int w0 = (int)floorf(sw);
        float th = sh - (float)h0;
        float tw = sw - (float)w0;
        int h0c = h0 < 0 ? 0 : h0;   int h1c = h0 + 1 > H3 - 1 ? H3 - 1 : h0 + 1;
        int w0c = w0 < 0 ? 0 : w0;   int w1c = w0 + 1 > W3 - 1 ? W3 - 1 : w0 + 1;
        const float* base = f3 + ((size_t)b * C3DIM + c3) * (H3 * W3);
        float v00 = base[h0c * W3 + w0c];
        float v01 = base[h0c * W3 + w1c];
        float v10 = base[h1c * W3 + w0c];
        float v11 = base[h1c * W3 + w1c];
        val = (1.f - th) * ((1.f - tw) * v00 + tw * v01)
            +        th  * ((1.f - tw) * v10 + tw * v11);
    }
    g_pat_bf[(size_t)n * CDIM + c] = __float2bfloat16(val);
}

// bank fp32 -> bf16 (+ zero pad rows) + squared norm of rounded values
__global__ void bankcvt_kernel(const float* __restrict__ bank) {
    int warp = (blockIdx.x * blockDim.x + threadIdx.x) >> 5;
    int lane = threadIdx.x & 31;
    if (warp >= MBANK_PAD) return;
    uint32_t* dst = (uint32_t*)(g_bank_bf + (size_t)warp * CDIM);
    if (warp >= MBANK) {
        #pragma unroll
        for (int j = 0; j < CDIM / 64; ++j) dst[j * 32 + lane] = 0u;
        if (lane == 0) g_msq[warp] = __int_as_float(0x7f800000);
        return;
    }
    const float2* src = (const float2*)(bank + (size_t)warp * CDIM);
    float s = 0.f;
    #pragma unroll
    for (int j = 0; j < CDIM / 64; ++j) {
        float2 v = src[j * 32 + lane];
        __nv_bfloat162 bv = __float22bfloat162_rn(v);
        dst[j * 32 + lane] = *(uint32_t*)&bv;
        float f0 = __bfloat162float(bv.x), f1 = __bfloat162float(bv.y);
        s += f0 * f0 + f1 * f1;
    }
    #pragma unroll
    for (int off = 16; off; off >>= 1) s += __shfl_xor_sync(0xffffffffu, s, off);
    if (lane == 0) g_msq[warp] = s;
}

__global__ void xsq_kernel() {
    int warp = (blockIdx.x * blockDim.x + threadIdx.x) >> 5;
    int lane = threadIdx.x & 31;
    if (warp >= NPATCH) return;
    const uint32_t* src = (const uint32_t*)(g_pat_bf + (size_t)warp * CDIM);
    float s = 0.f;
    #pragma unroll
    for (int j = 0; j < CDIM / 64; ++j) {
        uint32_t u = src[j * 32 + lane];
        __nv_bfloat162 bv = *(__nv_bfloat162*)&u;
        float f0 = __bfloat162float(bv.x), f1 = __bfloat162float(bv.y);
        s += f0 * f0 + f1 * f1;
    }
    #pragma unroll
    for (int off = 16; off; off >>= 1) s += __shfl_xor_sync(0xffffffffu, s, off);
    if (lane == 0) g_xsq[warp] = s;
}

// ============================ main GEMM+min kernel ============================
// 256 threads, 8 warps in 2(m) x 4(n); warp tile 64x64 via mma.m16n8k16 bf16.
__global__ void __launch_bounds__(256, 1) nn_kernel() {
    extern __shared__ __align__(1024) char smem[];
    char* Asm = smem;
    const int tid  = threadIdx.x;
    const int lane = tid & 31;
    const int wid  = tid >> 5;
    const int wm   = wid >> 2;      // 0..1
    const int wn   = wid & 3;       // 0..3
    const int n0   = blockIdx.x * TILE_M;
    const int split = blockIdx.y;
    const int mbase = split * (BTILES * TILE_N);

    const uint32_t aSm = s2u(smem);
    const uint32_t bSm = aSm + ABYTES;

    // ---- load A tile (128 x 384 bf16) into smem, stride 392 ----
    #pragma unroll
    for (int i = 0; i < 24; ++i) {
        int e = i * 256 + tid;
        int r = e / 48, q = e - r * 48;
        uint4 v = *(const uint4*)(g_pat_bf + (size_t)(n0 + r) * CDIM + q * 8);
        *(uint4*)(Asm + r * (ASTRIDE * 2) + q * 16) = v;
    }
    __syncthreads();

    // per-lane ldmatrix base addresses
    const uint32_t aBase = aSm +
        ((wm * 64 + (lane & 15)) * ASTRIDE + (lane >> 4) * 8) * 2;
    const int lq = lane >> 3;
    const int bn = (lane & 7) + ((lq >> 1) << 3);
    const int bk = (lq & 1) << 3;
    const uint32_t bBase = bSm + (wn * 64 + bn) * BROWB + bk * 2;

    float rowmin[4][2];
    #pragma unroll
    for (int i = 0; i < 4; ++i) {
        rowmin[i][0] = __int_as_float(0x7f800000);
        rowmin[i][1] = __int_as_float(0x7f800000);
    }

    // ---- chunk loader (cp.async, 256 rows x 64 k-cols bf16 = 32KB) ----
    auto load_chunk = [&](int cg) {
        int t  = cg / 6;
        int kc = cg - t * 6;
        const char* src0 = (const char*)(g_bank_bf +
                           (size_t)(mbase + t * TILE_N) * CDIM + kc * 64);
        uint32_t dbase = bSm + (uint32_t)(cg & 1) * BBUF;
        #pragma unroll
        for (int i = 0; i < 8; ++i) {
            int e = i * 256 + tid;
            int r = e >> 3, q = e & 7;
            uint32_t d = dbase + r * BROWB + q * 16;
            const char* s = src0 + (size_t)r * (CDIM * 2) + q * 16;
            asm volatile("cp.async.cg.shared.global [%0], [%1], 16;"
                         :: "r"(d), "l"(s));
        }
        asm volatile("cp.async.commit_group;");
    };

    load_chunk(0);

    int cg = 0;
    for (int t = 0; t < BTILES; ++t) {
        float acc[4][8][4];
        #pragma unroll
        for (int mt = 0; mt < 4; ++mt)
            #pragma unroll
            for (int nt = 0; nt < 8; ++nt)
                #pragma unroll
                for (int e = 0; e < 4; ++e) acc[mt][nt][e] = 0.f;

        #pragma unroll 1
        for (int j = 0; j < 6; ++j, ++cg) {
            if (cg + 1 < CHUNKS) {
                load_chunk(cg + 1);
                asm volatile("cp.async.wait_group 1;");
            } else {
                asm volatile("cp.async.wait_group 0;");
            }
            __syncthreads();

            const uint32_t bBuf = bBase + (uint32_t)(cg & 1) * BBUF;
            #pragma unroll
            for (int s = 0; s < 4; ++s) {
                // B frags: 4 x4-ldmatrix -> 8 n8-tiles x {b0,b1}
                uint32_t b[8][2];
                #pragma unroll
                for (int np = 0; np < 4; ++np) {
                    uint32_t r0, r1, r2, r3;
                    uint32_t ad = bBuf + np * (16 * BROWB) + s * 32;
                    asm volatile(
                        "ldmatrix.sync.aligned.m8n8.x4.shared.b16 "
                        "{%0,%1,%2,%3}, [%4];"
                        : "=r"(r0), "=r"(r1), "=r"(r2), "=r"(r3) : "r"(ad));
                    b[2 * np][0] = r0; b[2 * np][1] = r1;
                    b[2 * np + 1][0] = r2; b[2 * np + 1][1] = r3;
                }
                // A frags: 4 x4-ldmatrix -> 4 m16-tiles x {a0..a3}
                uint32_t a[4][4];
                #pragma unroll
                for (int mt = 0; mt < 4; ++mt) {
                    uint32_t ad = aBase + mt * (16 * ASTRIDE * 2)
                                + (j * 64 + s * 16) * 2;
                    asm volatile(
                        "ldmatrix.sync.aligned.m8n8.x4.shared.b16 "
                        "{%0,%1,%2,%3}, [%4];"
                        : "=r"(a[mt][0]), "=r"(a[mt][1]),
                          "=r"(a[mt][2]), "=r"(a[mt][3]) : "r"(ad));
                }
                #pragma unroll
                for (int mt = 0; mt < 4; ++mt)
                    #pragma unroll
                    for (int nt = 0; nt < 8; ++nt) {
                        asm volatile(
                            "mma.sync.aligned.m16n8k16.row.col.f32.bf16.bf16.f32 "
                            "{%0,%1,%2,%3}, {%4,%5,%6,%7}, {%8,%9}, {%0,%1,%2,%3};"
                            : "+f"(acc[mt][nt][0]), "+f"(acc[mt][nt][1]),
                              "+f"(acc[mt][nt][2]), "+f"(acc[mt][nt][3])
                            : "r"(a[mt][0]), "r"(a[mt][1]),
                              "r"(a[mt][2]), "r"(a[mt][3]),
                              "r"(b[nt][0]), "r"(b[nt][1]));
                    }
            }
            __syncthreads();
        }

        // ---- fold tile into persistent row-min regs ----
        const int cb = mbase + t * TILE_N + wn * 64 + (lane & 3) * 2;
        #pragma unroll
        for (int nt = 0; nt < 8; ++nt) {
            float m0 = __ldg(&g_msq[cb + nt * 8]);
            float m1 = __ldg(&g_msq[cb + nt * 8 + 1]);
            #pragma unroll
            for (int mt = 0; mt < 4; ++mt) {
                float v0 = fmaf(-2.f, acc[mt][nt][0], m0);
                float v1 = fmaf(-2.f, acc[mt][nt][1], m1);
                float v2 = fmaf(-2.f, acc[mt][nt][2], m0);
                float v3 = fmaf(-2.f, acc[mt][nt][3], m1);
                rowmin[mt][0] = fminf(rowmin[mt][0], fminf(v0, v1));
                rowmin[mt][1] = fminf(rowmin[mt][1], fminf(v2, v3));
            }
        }
    }

    // ---- final reduction: lanes sharing rows, then across wn warps ----
    #pragma unroll
    for (int mt = 0; mt < 4; ++mt)
        #pragma unroll
        for (int h = 0; h < 2; ++h) {
            float v = rowmin[mt][h];
            v = fminf(v, __shfl_xor_sync(0xffffffffu, v, 1));
            v = fminf(v, __shfl_xor_sync(0xffffffffu, v, 2));
            rowmin[mt][h] = v;
        }
    __syncthreads();
    float* red = (float*)Asm;      // [4 wn][128 rows], aliases A region
    if ((lane & 3) == 0) {
        #pragma unroll
        for (int mt = 0; mt < 4; ++mt)
            #pragma unroll
            for (int h = 0; h < 2; ++h) {
                int row = wm * 64 + mt * 16 + (lane >> 2) + h * 8;
                red[wn * 128 + row] = rowmin[mt][h];
            }
    }
    __syncthreads();
    if (tid < 128) {
        float v = fminf(fminf(red[tid], red[128 + tid]),
                        fminf(red[256 + tid], red[384 + tid]));
        g_part[split * NPATCH + n0 + tid] = v;
    }
}

// ============================ finalize ============================
__global__ void finalize_kernel(float* __restrict__ out) {
    int n = blockIdx.x * blockDim.x + threadIdx.x;
    if (n >= NPATCH) return;
    float m = fminf(g_part[n], fminf(g_part[NPATCH + n], g_part[2 * NPATCH + n]));
    float d2 = g_xsq[n] + m;
    d2 = fmaxf(d2, 1e-12f);
    out[n] = sqrtf(d2);
}

__global__ void img_max_kernel(float* __restrict__ out) {
    __shared__ float red[8];
    int b = blockIdx.x;
    int tid = threadIdx.x;
    float v = -3.0e38f;
    for (int i = tid; i < HDIM * WDIM; i += blockDim.x)
        v = fmaxf(v, out[b * (HDIM * WDIM) + i]);
    #pragma unroll
    for (int off = 16; off; off >>= 1)
        v = fmaxf(v, __shfl_xor_sync(0xffffffffu, v, off));
    if ((tid & 31) == 0) red[tid >> 5] = v;
    __syncthreads();
    if (tid < 8) {
        v = red[tid];
        #pragma unroll
        for (int off = 4; off; off >>= 1)
            v = fmaxf(v, __shfl_xor_sync(0x000000ffu, v, off));
        if (tid == 0) out[NPATCH + b] = v;
    }
}

// ============================ launch ============================
extern "C" void kernel_launch(void* const* d_in, const int* in_sizes, int n_in,
                              void* d_out, int out_size) {
    const float* f2   = (const float*)d_in[0];
    const float* f3   = (const float*)d_in[1];
    const float* bank = (const float*)d_in[2];
    float* out = (float*)d_out;

    cudaFuncSetAttribute(nn_kernel,
                         cudaFuncAttributeMaxDynamicSharedMemorySize, SM_TOTAL);

    embed_kernel<<<(NPATCH * CDIM + 255) / 256, 256>>>(f2, f3);
    bankcvt_kernel<<<(MBANK_PAD * 32 + 255) / 256, 256>>>(bank);
    xsq_kernel<<<(NPATCH * 32 + 255) / 256, 256>>>();

    dim3 grid(NTILES, MSPLIT);
    nn_kernel<<<grid, 256, SM_TOTAL>>>();

    finalize_kernel<<<(NPATCH + 255) / 256, 256>>>(out);
    if (out_size >= NPATCH + BATCH)
        img_max_kernel<<<BATCH, 256>>>(out);
}

// round 4
// speedup vs baseline: 18.6582x; 1.1057x over previous
#include <cuda_runtime.h>
#include <cuda_bf16.h>
#include <cstdint>

// ---------------- problem constants ----------------
#define BATCH   8
#define C2DIM   128
#define C3DIM   256
#define HDIM    28
#define WDIM    28
#define H3      14
#define W3      14
#define CDIM    384
#define NPATCH  6272
#define MBANK   30000
#define MBANK_PAD 30720             // 3 splits * 40 tiles * 256 rows

// ---------------- tiling ----------------
#define MSPLIT   3
#define TILE_M   128                // patches per CTA
#define TILE_N   256                // bank rows per CTA tile
#define NTILES   49                 // NPATCH / TILE_M
#define BTILES   40                 // bank tiles per split (40*256 = 10240)
#define CHUNKS   (BTILES * 6)       // k-chunks of 64 per split stream

#define ASTRIDE  392                // bf16 elems per A row (384 + 8 pad)
#define ABYTES   (128 * ASTRIDE * 2)    // 100352
#define BROWB    144                // bytes per B row (64 bf16 + 8 pad)
#define BBUF     (TILE_N * BROWB)   // 36864
#define SM_TOTAL (ABYTES + 2 * BBUF)    // 174080

#define NTHREADS 512

// ---------------- scratch ----------------
__device__ __align__(16) __nv_bfloat16 g_pat_bf[(size_t)NPATCH * CDIM];
__device__ __align__(16) __nv_bfloat16 g_bank_bf[(size_t)MBANK_PAD * CDIM];
__device__ float g_xsq[NPATCH];
__device__ float g_msq[MBANK_PAD];
__device__ float g_part[MSPLIT * NPATCH];

__device__ __forceinline__ uint32_t s2u(const void* p) {
    uint32_t r;
    asm("{ .reg .u64 t; cvta.to.shared.u64 t, %1; cvt.u32.u64 %0, t; }"
        : "=r"(r) : "l"(p));
    return r;
}

// ============================ prep kernels ============================
__global__ void embed_kernel(const float* __restrict__ f2,
                             const float* __restrict__ f3) {
    int idx = blockIdx.x * blockDim.x + threadIdx.x;
    if (idx >= NPATCH * CDIM) return;
    int n = idx / CDIM;
    int c = idx - n * CDIM;
    int b = n / (HDIM * WDIM);
    int hw = n - b * (HDIM * WDIM);
    int h = hw / WDIM;
    int w = hw - h * WDIM;

    float val;
    if (c < C2DIM) {
        val = f2[(((size_t)b * C2DIM + c) * HDIM + h) * WDIM + w];
    } else {
        int c3 = c - C2DIM;
        float sh = h * 0.5f - 0.25f;
        float sw = w * 0.5f - 0.25f;
        int h0 = (int)floorf(sh);
        int w0 = (int)floorf(sw);
        float th = sh - (float)h0;
        float tw = sw - (float)w0;
        int h0c = h0 < 0 ? 0 : h0;   int h1c = h0 + 1 > H3 - 1 ? H3 - 1 : h0 + 1;
        int w0c = w0 < 0 ? 0 : w0;   int w1c = w0 + 1 > W3 - 1 ? W3 - 1 : w0 + 1;
        const float* base = f3 + ((size_t)b * C3DIM + c3) * (H3 * W3);
        float v00 = base[h0c * W3 + w0c];
        float v01 = base[h0c * W3 + w1c];
        float v10 = base[h1c * W3 + w0c];
        float v11 = base[h1c * W3 + w1c];
        val = (1.f - th) * ((1.f - tw) * v00 + tw * v01)
            +        th  * ((1.f - tw) * v10 + tw * v11);
    }
    g_pat_bf[(size_t)n * CDIM + c] = __float2bfloat16(val);
}

// bank fp32 -> bf16 (+ zero pad rows) + squared norm of rounded values
__global__ void bankcvt_kernel(const float* __restrict__ bank) {
    int warp = (blockIdx.x * blockDim.x + threadIdx.x) >> 5;
    int lane = threadIdx.x & 31;
    if (warp >= MBANK_PAD) return;
    uint32_t* dst = (uint32_t*)(g_bank_bf + (size_t)warp * CDIM);
    if (warp >= MBANK) {
        #pragma unroll
        for (int j = 0; j < CDIM / 64; ++j) dst[j * 32 + lane] = 0u;
        if (lane == 0) g_msq[warp] = __int_as_float(0x7f800000);
        return;
    }
    const float2* src = (const float2*)(bank + (size_t)warp * CDIM);
    float s = 0.f;
    #pragma unroll
    for (int j = 0; j < CDIM / 64; ++j) {
        float2 v = src[j * 32 + lane];
        __nv_bfloat162 bv = __float22bfloat162_rn(v);
        dst[j * 32 + lane] = *(uint32_t*)&bv;
        float f0 = __bfloat162float(bv.x), f1 = __bfloat162float(bv.y);
        s += f0 * f0 + f1 * f1;
    }
    #pragma unroll
    for (int off = 16; off; off >>= 1) s += __shfl_xor_sync(0xffffffffu, s, off);
    if (lane == 0) g_msq[warp] = s;
}

__global__ void xsq_kernel() {
    int warp = (blockIdx.x * blockDim.x + threadIdx.x) >> 5;
    int lane = threadIdx.x & 31;
    if (warp >= NPATCH) return;
    const uint32_t* src = (const uint32_t*)(g_pat_bf + (size_t)warp * CDIM);
    float s = 0.f;
    #pragma unroll
    for (int j = 0; j < CDIM / 64; ++j) {
        uint32_t u = src[j * 32 + lane];
        __nv_bfloat162 bv = *(__nv_bfloat162*)&u;
        float f0 = __bfloat162float(bv.x), f1 = __bfloat162float(bv.y);
        s += f0 * f0 + f1 * f1;
    }
    #pragma unroll
    for (int off = 16; off; off >>= 1) s += __shfl_xor_sync(0xffffffffu, s, off);
    if (lane == 0) g_xsq[warp] = s;
}

// ============================ main GEMM+min kernel ============================
// 512 threads, 16 warps in 2(m) x 8(n); warp tile 64x32 via mma.m16n8k16 bf16.
__global__ void __launch_bounds__(NTHREADS, 1) nn_kernel() {
    extern __shared__ __align__(1024) char smem[];
    char* Asm = smem;
    const int tid  = threadIdx.x;
    const int lane = tid & 31;
    const int wid  = tid >> 5;
    const int wm   = wid >> 3;      // 0..1
    const int wn   = wid & 7;       // 0..7
    const int n0   = blockIdx.x * TILE_M;
    const int split = blockIdx.y;
    const int mbase = split * (BTILES * TILE_N);

    const uint32_t aSm = s2u(smem);
    const uint32_t bSm = aSm + ABYTES;

    // ---- load A tile (128 x 384 bf16) into smem, stride 392 ----
    #pragma unroll
    for (int i = 0; i < 12; ++i) {
        int e = i * NTHREADS + tid;
        int r = e / 48, q = e - r * 48;
        uint4 v = *(const uint4*)(g_pat_bf + (size_t)(n0 + r) * CDIM + q * 8);
        *(uint4*)(Asm + r * (ASTRIDE * 2) + q * 16) = v;
    }

    // per-lane ldmatrix base addresses
    const uint32_t aBase = aSm +
        ((wm * 64 + (lane & 15)) * ASTRIDE + (lane >> 4) * 8) * 2;
    const int lq = lane >> 3;
    const int bn = (lane & 7) + ((lq >> 1) << 3);
    const int bk = (lq & 1) << 3;
    const uint32_t bBase = bSm + (wn * 32 + bn) * BROWB + bk * 2;

    float rowmin[4][2];
    #pragma unroll
    for (int i = 0; i < 4; ++i) {
        rowmin[i][0] = __int_as_float(0x7f800000);
        rowmin[i][1] = __int_as_float(0x7f800000);
    }

    // ---- chunk loader (cp.async, 256 rows x 64 k-cols bf16 = 32KB) ----
    auto load_chunk = [&](int cg) {
        int t  = cg / 6;
        int kc = cg - t * 6;
        const char* src0 = (const char*)(g_bank_bf +
                           (size_t)(mbase + t * TILE_N) * CDIM + kc * 64);
        uint32_t dbase = bSm + (uint32_t)(cg & 1) * BBUF;
        #pragma unroll
        for (int i = 0; i < 4; ++i) {
            int e = i * NTHREADS + tid;
            int r = e >> 3, q = e & 7;
            uint32_t d = dbase + r * BROWB + q * 16;
            const char* s = src0 + (size_t)r * (CDIM * 2) + q * 16;
            asm volatile("cp.async.cg.shared.global [%0], [%1], 16;"
                         :: "r"(d), "l"(s));
        }
        asm volatile("cp.async.commit_group;");
    };

    load_chunk(0);
    __syncthreads();   // also covers the A-tile stores

    int cg = 0;
    for (int t = 0; t < BTILES; ++t) {
        float acc[4][4][4];
        #pragma unroll
        for (int mt = 0; mt < 4; ++mt)
            #pragma unroll
            for (int nt = 0; nt < 4; ++nt)
                #pragma unroll
                for (int e = 0; e < 4; ++e) acc[mt][nt][e] = 0.f;

        #pragma unroll 1
        for (int j = 0; j < 6; ++j, ++cg) {
            asm volatile("cp.async.wait_group 0;");
            __syncthreads();               // buf[cg&1] visible; prev compute done
            if (cg + 1 < CHUNKS) load_chunk(cg + 1);

            const uint32_t bBuf = bBase + (uint32_t)(cg & 1) * BBUF;
            #pragma unroll
            for (int s = 0; s < 4; ++s) {
                // B frags: 2 x4-ldmatrix -> 4 n8-tiles x {b0,b1}
                uint32_t b[4][2];
                #pragma unroll
                for (int np = 0; np < 2; ++np) {
                    uint32_t r0, r1, r2, r3;
                    uint32_t ad = bBuf + np * (16 * BROWB) + s * 32;
                    asm volatile(
                        "ldmatrix.sync.aligned.m8n8.x4.shared.b16 "
                        "{%0,%1,%2,%3}, [%4];"
                        : "=r"(r0), "=r"(r1), "=r"(r2), "=r"(r3) : "r"(ad));
                    b[2 * np][0] = r0; b[2 * np][1] = r1;
                    b[2 * np + 1][0] = r2; b[2 * np + 1][1] = r3;
                }
                // A frags: 4 x4-ldmatrix -> 4 m16-tiles x {a0..a3}
                uint32_t a[4][4];
                #pragma unroll
                for (int mt = 0; mt < 4; ++mt) {
                    uint32_t ad = aBase + mt * (16 * ASTRIDE * 2)
                                + (j * 64 + s * 16) * 2;
                    asm volatile(
                        "ldmatrix.sync.aligned.m8n8.x4.shared.b16 "
                        "{%0,%1,%2,%3}, [%4];"
                        : "=r"(a[mt][0]), "=r"(a[mt][1]),
                          "=r"(a[mt][2]), "=r"(a[mt][3]) : "r"(ad));
                }
                #pragma unroll
                for (int mt = 0; mt < 4; ++mt)
                    #pragma unroll
                    for (int nt = 0; nt < 4; ++nt) {
                        asm volatile(
                            "mma.sync.aligned.m16n8k16.row.col.f32.bf16.bf16.f32 "
                            "{%0,%1,%2,%3}, {%4,%5,%6,%7}, {%8,%9}, {%0,%1,%2,%3};"
                            : "+f"(acc[mt][nt][0]), "+f"(acc[mt][nt][1]),
                              "+f"(acc[mt][nt][2]), "+f"(acc[mt][nt][3])
                            : "r"(a[mt][0]), "r"(a[mt][1]),
                              "r"(a[mt][2]), "r"(a[mt][3]),
                              "r"(b[nt][0]), "r"(b[nt][1]));
                    }
            }
        }

        // ---- fold tile into persistent row-min regs ----
        const int cb = mbase + t * TILE_N + wn * 32 + (lane & 3) * 2;
        #pragma unroll
        for (int nt = 0; nt < 4; ++nt) {
            float m0 = __ldg(&g_msq[cb + nt * 8]);
            float m1 = __ldg(&g_msq[cb + nt * 8 + 1]);
            #pragma unroll
            for (int mt = 0; mt < 4; ++mt) {
                float v0 = fmaf(-2.f, acc[mt][nt][0], m0);
                float v1 = fmaf(-2.f, acc[mt][nt][1], m1);
                float v2 = fmaf(-2.f, acc[mt][nt][2], m0);
                float v3 = fmaf(-2.f, acc[mt][nt][3], m1);
                rowmin[mt][0] = fminf(rowmin[mt][0], fminf(v0, v1));
                rowmin[mt][1] = fminf(rowmin[mt][1], fminf(v2, v3));
            }
        }
    }

    // ---- final reduction: lanes sharing rows, then across wn warps ----
    #pragma unroll
    for (int mt = 0; mt < 4; ++mt)
        #pragma unroll
        for (int h = 0; h < 2; ++h) {
            float v = rowmin[mt][h];
            v = fminf(v, __shfl_xor_sync(0xffffffffu, v, 1));
            v = fminf(v, __shfl_xor_sync(0xffffffffu, v, 2));
            rowmin[mt][h] = v;
        }
    __syncthreads();
    float* red = (float*)Asm;      // [8 wn][128 rows], aliases A region
    if ((lane & 3) == 0) {
        #pragma unroll
        for (int mt = 0; mt < 4; ++mt)
            #pragma unroll
            for (int h = 0; h < 2; ++h) {
                int row = wm * 64 + mt * 16 + (lane >> 2) + h * 8;
                red[wn * 128 + row] = rowmin[mt][h];
            }
    }
    __syncthreads();
    if (tid < 128) {
        float v = red[tid];
        #pragma unroll
        for (int wq = 1; wq < 8; ++wq)
            v = fminf(v, red[wq * 128 + tid]);
        g_part[split * NPATCH + n0 + tid] = v;
    }
}

// ============================ finalize ============================
__global__ void finalize_kernel(float* __restrict__ out) {
    int n = blockIdx.x * blockDim.x + threadIdx.x;
    if (n >= NPATCH) return;
    float m = fminf(g_part[n], fminf(g_part[NPATCH + n], g_part[2 * NPATCH + n]));
    float d2 = g_xsq[n] + m;
    d2 = fmaxf(d2, 1e-12f);
    out[n] = sqrtf(d2);
}

__global__ void img_max_kernel(float* __restrict__ out) {
    __shared__ float red[8];
    int b = blockIdx.x;
    int tid = threadIdx.x;
    float v = -3.0e38f;
    for (int i = tid; i < HDIM * WDIM; i += blockDim.x)
        v = fmaxf(v, out[b * (HDIM * WDIM) + i]);
    #pragma unroll
    for (int off = 16; off; off >>= 1)
        v = fmaxf(v, __shfl_xor_sync(0xffffffffu, v, off));
    if ((tid & 31) == 0) red[tid >> 5] = v;
    __syncthreads();
    if (tid < 8) {
        v = red[tid];
        #pragma unroll
        for (int off = 4; off; off >>= 1)
            v = fmaxf(v, __shfl_xor_sync(0x000000ffu, v, off));
        if (tid == 0) out[NPATCH + b] = v;
    }
}

// ============================ launch ============================
extern "C" void kernel_launch(void* const* d_in, const int* in_sizes, int n_in,
                              void* d_out, int out_size) {
    const float* f2   = (const float*)d_in[0];
    const float* f3   = (const float*)d_in[1];
    const float* bank = (const float*)d_in[2];
    float* out = (float*)d_out;

    cudaFuncSetAttribute(nn_kernel,
                         cudaFuncAttributeMaxDynamicSharedMemorySize, SM_TOTAL);

    embed_kernel<<<(NPATCH * CDIM + 255) / 256, 256>>>(f2, f3);
    bankcvt_kernel<<<(MBANK_PAD * 32 + 255) / 256, 256>>>(bank);
    xsq_kernel<<<(NPATCH * 32 + 255) / 256, 256>>>();

    dim3 grid(NTILES, MSPLIT);
    nn_kernel<<<grid, NTHREADS, SM_TOTAL>>>();

    finalize_kernel<<<(NPATCH + 255) / 256, 256>>>(out);
    if (out_size >= NPATCH + BATCH)
        img_max_kernel<<<BATCH, 256>>>(out);
}